// round 15
// baseline (speedup 1.0000x reference)
#include <cuda_runtime.h>
#include <cuda_fp16.h>

#define SD 1024          // structure points per batch (rows)
#define NP 16384         // gt points per batch (cols)
#define NJOB 24
#define NBLK 592         // 148 SMs x 4 resident blocks: one perfectly even wave
#define TOTC (NJOB * NP) // 393216 flattened columns

// scratch — ZERO-initialized at module load; reset inline after each read,
// so every kernel_launch call (and every graph replay) starts from zeros.
// g_rowmin holds keys: key = 0x7f800000 - float_bits(q), q >= 0. key 0 == q = +inf.
__device__ __align__(16) int g_rowmin[24576]; // 8*1024 (cham1) + 16*1024 (cham2)
__device__ float g_acc[8];  // [0]=colsum1 [1]=colsum2 [2]=mse [4]=rowsum1 [5]=rowsum2

__device__ __forceinline__ unsigned h2u(__half2 h) {
    return *reinterpret_cast<unsigned*>(&h);
}
__device__ __forceinline__ unsigned umin16x2(unsigned a, unsigned b) {
    unsigned d;
    asm("min.u16x2 %0, %1, %2;" : "=r"(d) : "r"(a), "r"(b));
    return d;
}
__device__ __forceinline__ float h_lo(unsigned v) {
    return __half2float(__ushort_as_half((unsigned short)(v & 0xffffu)));
}
__device__ __forceinline__ float h_hi(unsigned v) {
    return __half2float(__ushort_as_half((unsigned short)(v >> 16)));
}

// merged chamfer, flat column partition: block b owns flattened columns
// [b*TOTC/NBLK, (b+1)*TOTC/NBLK); each warp owns a quarter of that.
// Flattened col f -> job f/NP, local col f%NP. Jobs 0..15 = (tsp,tgt), 16..23 = (sp,gt).
__global__ __launch_bounds__(128, 4)
void k_chamfer(const float* __restrict__ sp,  const float* __restrict__ gt,
               const float* __restrict__ tsp, const float* __restrict__ tgt)
{
    __shared__ uint4 tile[4][32];   // per column: {xx, yy, zz, hh} as half2 dups

    const int tid  = threadIdx.x;
    const int lane = tid & 31;
    const int warp = tid >> 5;
    const unsigned UBIG = 0x7bff7bffu;  // fp16 max in both halves

    const int c0   = (int)((long long)blockIdx.x * TOTC / NBLK);
    const int c1   = (int)((long long)(blockIdx.x + 1) * TOTC / NBLK);
    const int span = c1 - c0;
    const int w0   = c0 + (span * warp) / 4;
    const int w1   = c0 + (span * (warp + 1)) / 4;

    int s0 = w0;
    while (s0 < w1) {
        const int job = s0 / NP;
        const int s1  = min(w1, (job + 1) * NP);

        const float* pa; const float* pb; int rowoff, acc_idx;
        if (job < 16) { pa = tsp + (size_t)job * SD * 3;  pb = tgt + (size_t)job * NP * 3;
                        rowoff = 8192 + job * SD;         acc_idx = 1; }
        else          { int bb = job - 16;
                        pa = sp + (size_t)bb * SD * 3;    pb = gt + (size_t)bb * NP * 3;
                        rowoff = bb * SD;                 acc_idx = 0; }

        // ---- all 1024 rows of this job in this warp's registers (half2) ----
        // unit i packs rows (2i)*32+lane (lo half) and (2i+1)*32+lane (hi half)
        __half2 nax2[16], nay2[16], naz2[16], ha2[16];
        unsigned rl[16];
#pragma unroll
        for (int i = 0; i < 16; i++) {
            int r0 = (2 * i) * 32 + lane;
            int r1 = r0 + 32;
            float x0 = pa[r0*3+0], y0 = pa[r0*3+1], z0 = pa[r0*3+2];
            float x1 = pa[r1*3+0], y1 = pa[r1*3+1], z1 = pa[r1*3+2];
            nax2[i] = __floats2half2_rn(-x0, -x1);
            nay2[i] = __floats2half2_rn(-y0, -y1);
            naz2[i] = __floats2half2_rn(-z0, -z1);
            ha2[i]  = __floats2half2_rn(0.5f * (x0*x0 + y0*y0 + z0*z0),
                                        0.5f * (x1*x1 + y1*y1 + z1*z1));
            rl[i] = UBIG;
        }

        float csum = 0.0f;
        const int colbase = job * NP;

        for (int ts = s0; ts < s1; ts += 32) {
            {   // stage: duplicated half2 packs; invalid lanes get hb=fp16max
                int c = ts + lane;
                uint4 v;
                if (c < s1) {
                    int cl = c - colbase;
                    float cx = pb[cl*3+0], cy = pb[cl*3+1], cz = pb[cl*3+2];
                    float hb = 0.5f * (cx*cx + cy*cy + cz*cz);
                    v.x = h2u(__float2half2_rn(cx));
                    v.y = h2u(__float2half2_rn(cy));
                    v.z = h2u(__float2half2_rn(cz));
                    v.w = h2u(__float2half2_rn(hb));
                } else {
                    v = make_uint4(0u, 0u, 0u, UBIG);   // q = ha + 60000: harmless
                }
                tile[warp][lane] = v;
            }
            __syncwarp();

            // systolic: at step j, lane l owns the accumulator for column (j+l)&31.
            // q = ha + hb - dot(a,b) (= dist^2/2) in half2 (fma pipe);
            // mins as u16x2 integer min (valid for q >= 0, fp16-noise safe).
            unsigned acc = UBIG;
#pragma unroll 2
            for (int j = 0; j < 32; j++) {
                int idx = (j + lane) & 31;
                uint4 P = tile[warp][idx];
                __half2 px2 = *reinterpret_cast<__half2*>(&P.x);
                __half2 py2 = *reinterpret_cast<__half2*>(&P.y);
                __half2 pz2 = *reinterpret_cast<__half2*>(&P.z);
                __half2 hb2 = *reinterpret_cast<__half2*>(&P.w);
                unsigned c0m = UBIG, c1m = UBIG, c2m = UBIG, c3m = UBIG;
#pragma unroll
                for (int i = 0; i < 16; i += 4) {
                    unsigned q0 = h2u(__hadd2(__hfma2(nax2[i+0], px2,
                                  __hfma2(nay2[i+0], py2,
                                  __hfma2(naz2[i+0], pz2, ha2[i+0]))), hb2));
                    rl[i+0] = umin16x2(rl[i+0], q0);  c0m = umin16x2(c0m, q0);
                    unsigned q1 = h2u(__hadd2(__hfma2(nax2[i+1], px2,
                                  __hfma2(nay2[i+1], py2,
                                  __hfma2(naz2[i+1], pz2, ha2[i+1]))), hb2));
                    rl[i+1] = umin16x2(rl[i+1], q1);  c1m = umin16x2(c1m, q1);
                    unsigned q2 = h2u(__hadd2(__hfma2(nax2[i+2], px2,
                                  __hfma2(nay2[i+2], py2,
                                  __hfma2(naz2[i+2], pz2, ha2[i+2]))), hb2));
                    rl[i+2] = umin16x2(rl[i+2], q2);  c2m = umin16x2(c2m, q2);
                    unsigned q3 = h2u(__hadd2(__hfma2(nax2[i+3], px2,
                                  __hfma2(nay2[i+3], py2,
                                  __hfma2(naz2[i+3], pz2, ha2[i+3]))), hb2));
                    rl[i+3] = umin16x2(rl[i+3], q3);  c3m = umin16x2(c3m, q3);
                }
                acc = umin16x2(acc, umin16x2(umin16x2(c0m, c1m), umin16x2(c2m, c3m)));
                acc = __shfl_sync(0xffffffffu, acc, (lane + 1) & 31);
            }
            // lane l holds the complete 1024-row min of column ts+l (both halves)
            if (ts + lane < s1)
                csum += fminf(fmaxf(h_lo(acc), 0.0f), fmaxf(h_hi(acc), 0.0f));
            __syncwarp();
        }

        // ---- flush this job segment ----
#pragma unroll
        for (int o = 16; o > 0; o >>= 1)
            csum += __shfl_xor_sync(0xffffffffu, csum, o);
        if (lane == 0) atomicAdd(&g_acc[acc_idx], csum);

        // partial row-mins -> global as max-keys (zero-init friendly):
        // key = 0x7f800000 - float_bits(max(q,0));  atomicMax picks smallest q.
        int* rm = g_rowmin + rowoff;
#pragma unroll
        for (int i = 0; i < 16; i++) {
            int r0 = (2 * i) * 32 + lane;
            float q0 = fmaxf(h_lo(rl[i]), 0.0f);
            float q1 = fmaxf(h_hi(rl[i]), 0.0f);
            atomicMax(&rm[r0],      0x7f800000 - __float_as_int(q0));
            atomicMax(&rm[r0 + 32], 0x7f800000 - __float_as_int(q1));
        }

        s0 = s1;
    }
}

// parallel reduction: consistency MSE + row-min key sums; resets row-min slots.
__global__ __launch_bounds__(256)
void k_red(const float* __restrict__ sp,
           const float* __restrict__ tsp,
           const float* __restrict__ M)
{
    const int gid = blockIdx.x * 256 + threadIdx.x;   // 48*256 = 12288 threads
    const int lane = threadIdx.x & 31;

    // consistency: tmp[t,b,s,e] = sum_d sp[b,s,d]*M[t,d,e]; SSE vs tsp
    float e = 0.0f;
    for (int idx = gid; idx < 16384; idx += 12288) {
        int t  = idx >> 13;
        int bs = idx & 8191;
        const float* p = sp + (size_t)bs * 3;
        float x = p[0], y = p[1], z = p[2];
        const float* m = M + t * 9;
        const float* q = tsp + (size_t)idx * 3;
#pragma unroll
        for (int cc = 0; cc < 3; cc++) {
            float v = fmaf(x, m[cc], fmaf(y, m[3 + cc], z * m[6 + cc]));
            float d = v - q[cc];
            e = fmaf(d, d, e);
        }
    }

    // row-min key sums: 6144 int4 (first 2048 = chamfer1); reset after read.
    int4* rm4 = (int4*)g_rowmin;
    float a1 = 0.0f, a2 = 0.0f;
    for (int i = gid; i < 6144; i += 12288) {
        int4 v = rm4[i];
        float s = __int_as_float(0x7f800000 - v.x) + __int_as_float(0x7f800000 - v.y)
                + __int_as_float(0x7f800000 - v.z) + __int_as_float(0x7f800000 - v.w);
        rm4[i] = make_int4(0, 0, 0, 0);
        if (i < 2048) a1 += s; else a2 += s;
    }

    // warp reduce + one atomicAdd per warp per accumulator
#pragma unroll
    for (int o = 16; o > 0; o >>= 1) {
        e  += __shfl_xor_sync(0xffffffffu, e,  o);
        a1 += __shfl_xor_sync(0xffffffffu, a1, o);
        a2 += __shfl_xor_sync(0xffffffffu, a2, o);
    }
    if (lane == 0) {
        atomicAdd(&g_acc[2], e);
        atomicAdd(&g_acc[4], a1);
        atomicAdd(&g_acc[5], a2);
    }
}

// combine + reset accumulators
__global__ __launch_bounds__(32)
void k_out(float* __restrict__ out)
{
    if (threadIdx.x == 0) {
        float cs1 = g_acc[0], cs2 = g_acc[1], mse = g_acc[2];
        float rs1 = g_acc[4], rs2 = g_acc[5];
        // t-space = dist^2/2; cd = mean_rowmin_t + mean_colmin_t
        float cd1 = rs1 / 8192.0f  + cs1 / 131072.0f;   // 8*1024, 8*16384
        float cd2 = rs2 / 16384.0f + cs2 / 262144.0f;   // 16*1024, 16*16384
        float consist = mse * (1000.0f / 49152.0f);     // mean over T*B*S*D
        out[0] = (cd1 + cd2) / 3.0f + consist;          // /(T+1)
#pragma unroll
        for (int i = 0; i < 8; i++) g_acc[i] = 0.0f;    // reset for next call
    }
}

extern "C" void kernel_launch(void* const* d_in, const int* in_sizes, int n_in,
                              void* d_out, int out_size) {
    const float* gt  = (const float*)d_in[0];   // [8,16384,3]
    const float* sp  = (const float*)d_in[1];   // [8,1024,3]
    const float* tgt = (const float*)d_in[2];   // [2,8,16384,3] -> 16 batches
    const float* tsp = (const float*)d_in[3];   // [2,8,1024,3]  -> 16 batches
    const float* M   = (const float*)d_in[4];   // [2,3,3]
    (void)in_sizes; (void)n_in; (void)out_size;

    k_chamfer<<<NBLK, 128>>>(sp, gt, tsp, tgt);
    k_red<<<48, 256>>>(sp, tsp, M);
    k_out<<<1, 32>>>((float*)d_out);
}

// round 16
// speedup vs baseline: 1.8800x; 1.8800x over previous
#include <cuda_runtime.h>
#include <cuda_fp16.h>

#define SD 1024          // structure points per batch (rows)
#define NP 16384         // gt points per batch (cols)
#define WC 64            // columns per warp per chunk
#define WARPS 4
#define COLS_PER_BLOCK (WARPS * WC)   // 256
#define XGRP 24          // x-groups per batch; 576 blocks total
#define REDBLKS 48

// scratch — ZERO-initialized at module load; reset inline after each read,
// so every kernel_launch call (and every graph replay) starts from zeros.
// g_rowmin holds keys: key = 0x7f800000 - float_bits(q), q >= 0. key 0 == q = +inf.
__device__ __align__(16) int g_rowmin[24576]; // 8*1024 (cham1) + 16*1024 (cham2)
__device__ float g_acc[8];  // [0]=colsum1 [1]=colsum2 [2]=mse [4]=rowsum1 [5]=rowsum2
__device__ int   g_done;    // k_red completion counter (self-resetting)

__device__ __forceinline__ unsigned h2u(__half2 h) {
    return *reinterpret_cast<unsigned*>(&h);
}
__device__ __forceinline__ unsigned umin16x2(unsigned a, unsigned b) {
    unsigned d;
    asm("min.u16x2 %0, %1, %2;" : "=r"(d) : "r"(a), "r"(b));
    return d;
}
__device__ __forceinline__ float h_lo(unsigned v) {
    return __half2float(__ushort_as_half((unsigned short)(v & 0xffffu)));
}
__device__ __forceinline__ float h_hi(unsigned v) {
    return __half2float(__ushort_as_half((unsigned short)(v >> 16)));
}

// merged chamfer, single wave: blockIdx.y in [0,24) selects job;
// blockIdx.x = j in [0,24) processes column-chunks {j, j+24, j+48} (each 256 cols).
__global__ __launch_bounds__(WARPS * 32)
void k_chamfer(const float* __restrict__ sp,  const float* __restrict__ gt,
               const float* __restrict__ tsp, const float* __restrict__ tgt)
{
    __shared__ uint4 tile[WARPS][32];   // per column: {xx, yy, zz, hh} as half2 dups

    const int y    = blockIdx.y;
    const int jg   = blockIdx.x;        // x-group
    const int tid  = threadIdx.x;
    const int lane = tid & 31;
    const int warp = tid >> 5;
    const unsigned UBIG = 0x7bff7bffu;  // fp16 max in both halves

    const float* pa; const float* pb; int rowoff, acc_idx;
    if (y < 16) { pa = tsp + (size_t)y * SD * 3;       pb = tgt + (size_t)y * NP * 3;
                  rowoff = 8192 + y * SD;              acc_idx = 1; }
    else        { int b = y - 16;
                  pa = sp + (size_t)b * SD * 3;        pb = gt + (size_t)b * NP * 3;
                  rowoff = b * SD;                     acc_idx = 0; }

    // ---- all 1024 rows of this batch in this warp's registers (half2) ----
    // unit i packs rows (2i)*32+lane (lo half) and (2i+1)*32+lane (hi half)
    __half2 nax2[16], nay2[16], naz2[16], ha2[16];
    unsigned rl[16];
#pragma unroll
    for (int i = 0; i < 16; i++) {
        int r0 = (2 * i) * 32 + lane;
        int r1 = r0 + 32;
        float x0 = pa[r0*3+0], y0 = pa[r0*3+1], z0 = pa[r0*3+2];
        float x1 = pa[r1*3+0], y1 = pa[r1*3+1], z1 = pa[r1*3+2];
        nax2[i] = __floats2half2_rn(-x0, -x1);
        nay2[i] = __floats2half2_rn(-y0, -y1);
        naz2[i] = __floats2half2_rn(-z0, -z1);
        ha2[i]  = __floats2half2_rn(0.5f * (x0*x0 + y0*y0 + z0*z0),
                                    0.5f * (x1*x1 + y1*y1 + z1*z1));
        rl[i] = UBIG;
    }

    float csum = 0.0f;
    const int nchunks = (jg < 16) ? 3 : 2;   // chunks jg, jg+24, jg+48 (<64)

    for (int k = 0; k < nchunks; k++) {
        const int cbase = (jg + 24 * k) * COLS_PER_BLOCK + warp * WC;

        // prefetch first tile's column of this chunk
        int c = cbase + lane;
        float cx = pb[c*3+0], cy = pb[c*3+1], cz = pb[c*3+2];

#pragma unroll
        for (int t = 0; t < WC / 32; t++) {
            {   // stage: duplicated half2 packs, 16 B per column
                float hb = 0.5f * (cx*cx + cy*cy + cz*cz);
                uint4 v;
                v.x = h2u(__float2half2_rn(cx));
                v.y = h2u(__float2half2_rn(cy));
                v.z = h2u(__float2half2_rn(cz));
                v.w = h2u(__float2half2_rn(hb));
                tile[warp][lane] = v;
            }
            __syncwarp();
            if (t + 1 < WC / 32) {           // prefetch next tile from gmem
                int cn = cbase + (t + 1) * 32 + lane;
                cx = pb[cn*3+0]; cy = pb[cn*3+1]; cz = pb[cn*3+2];
            }

            // systolic: at step j, lane l owns the accumulator for column (j+l)&31.
            // q = ha + hb - dot(a,b) (= dist^2/2) in half2 (fma pipe);
            // mins as u16x2 integer min (valid for q >= 0, fp16-noise safe).
            unsigned acc = UBIG;
#pragma unroll 2
            for (int j = 0; j < 32; j++) {
                int idx = (j + lane) & 31;
                uint4 P = tile[warp][idx];
                __half2 px2 = *reinterpret_cast<__half2*>(&P.x);
                __half2 py2 = *reinterpret_cast<__half2*>(&P.y);
                __half2 pz2 = *reinterpret_cast<__half2*>(&P.z);
                __half2 hb2 = *reinterpret_cast<__half2*>(&P.w);
                unsigned c0 = UBIG, c1 = UBIG, c2 = UBIG, c3 = UBIG;
#pragma unroll
                for (int i = 0; i < 16; i += 4) {
                    unsigned q0 = h2u(__hadd2(__hfma2(nax2[i+0], px2,
                                  __hfma2(nay2[i+0], py2,
                                  __hfma2(naz2[i+0], pz2, ha2[i+0]))), hb2));
                    rl[i+0] = umin16x2(rl[i+0], q0);  c0 = umin16x2(c0, q0);
                    unsigned q1 = h2u(__hadd2(__hfma2(nax2[i+1], px2,
                                  __hfma2(nay2[i+1], py2,
                                  __hfma2(naz2[i+1], pz2, ha2[i+1]))), hb2));
                    rl[i+1] = umin16x2(rl[i+1], q1);  c1 = umin16x2(c1, q1);
                    unsigned q2 = h2u(__hadd2(__hfma2(nax2[i+2], px2,
                                  __hfma2(nay2[i+2], py2,
                                  __hfma2(naz2[i+2], pz2, ha2[i+2]))), hb2));
                    rl[i+2] = umin16x2(rl[i+2], q2);  c2 = umin16x2(c2, q2);
                    unsigned q3 = h2u(__hadd2(__hfma2(nax2[i+3], px2,
                                  __hfma2(nay2[i+3], py2,
                                  __hfma2(naz2[i+3], pz2, ha2[i+3]))), hb2));
                    rl[i+3] = umin16x2(rl[i+3], q3);  c3 = umin16x2(c3, q3);
                }
                acc = umin16x2(acc, umin16x2(umin16x2(c0, c1), umin16x2(c2, c3)));
                acc = __shfl_sync(0xffffffffu, acc, (lane + 1) & 31);
            }
            // lane l: complete 1024-row min of column l of this tile (both halves)
            csum += fminf(fmaxf(h_lo(acc), 0.0f), fmaxf(h_hi(acc), 0.0f));
            __syncwarp();
        }
    }

    // per-warp sum of column mins -> one atomicAdd
#pragma unroll
    for (int o = 16; o > 0; o >>= 1)
        csum += __shfl_xor_sync(0xffffffffu, csum, o);
    if (lane == 0) atomicAdd(&g_acc[acc_idx], csum);

    // partial row-mins -> global as max-keys (zero-init friendly):
    // key = 0x7f800000 - float_bits(max(q,0));  atomicMax picks smallest q.
    int* rm = g_rowmin + rowoff;
#pragma unroll
    for (int i = 0; i < 16; i++) {
        int r0 = (2 * i) * 32 + lane;
        float q0 = fmaxf(h_lo(rl[i]), 0.0f);
        float q1 = fmaxf(h_hi(rl[i]), 0.0f);
        atomicMax(&rm[r0],      0x7f800000 - __float_as_int(q0));
        atomicMax(&rm[r0 + 32], 0x7f800000 - __float_as_int(q1));
    }
}

// parallel reduction: consistency MSE + row-min key sums; resets row-min slots.
// The LAST block to finish also combines the accumulators, writes out[0],
// and resets g_acc/g_done (self-resetting -> graph-replay deterministic).
__global__ __launch_bounds__(256)
void k_red(const float* __restrict__ sp,
           const float* __restrict__ tsp,
           const float* __restrict__ M,
           float* __restrict__ out)
{
    const int gid = blockIdx.x * 256 + threadIdx.x;   // 48*256 = 12288 threads
    const int lane = threadIdx.x & 31;

    // consistency: tmp[t,b,s,e] = sum_d sp[b,s,d]*M[t,d,e]; SSE vs tsp
    float e = 0.0f;
    for (int idx = gid; idx < 16384; idx += 12288) {
        int t  = idx >> 13;
        int bs = idx & 8191;
        const float* p = sp + (size_t)bs * 3;
        float x = p[0], y = p[1], z = p[2];
        const float* m = M + t * 9;
        const float* q = tsp + (size_t)idx * 3;
#pragma unroll
        for (int cc = 0; cc < 3; cc++) {
            float v = fmaf(x, m[cc], fmaf(y, m[3 + cc], z * m[6 + cc]));
            float d = v - q[cc];
            e = fmaf(d, d, e);
        }
    }

    // row-min key sums: 6144 int4 (first 2048 = chamfer1); reset after read.
    int4* rm4 = (int4*)g_rowmin;
    float a1 = 0.0f, a2 = 0.0f;
    for (int i = gid; i < 6144; i += 12288) {
        int4 v = rm4[i];
        float s = __int_as_float(0x7f800000 - v.x) + __int_as_float(0x7f800000 - v.y)
                + __int_as_float(0x7f800000 - v.z) + __int_as_float(0x7f800000 - v.w);
        rm4[i] = make_int4(0, 0, 0, 0);
        if (i < 2048) a1 += s; else a2 += s;
    }

    // warp reduce + one atomicAdd per warp per accumulator
#pragma unroll
    for (int o = 16; o > 0; o >>= 1) {
        e  += __shfl_xor_sync(0xffffffffu, e,  o);
        a1 += __shfl_xor_sync(0xffffffffu, a1, o);
        a2 += __shfl_xor_sync(0xffffffffu, a2, o);
    }
    if (lane == 0) {
        atomicAdd(&g_acc[2], e);
        atomicAdd(&g_acc[4], a1);
        atomicAdd(&g_acc[5], a2);
    }

    // last-block-done epilogue (replaces the k_out launch)
    __syncthreads();
    if (threadIdx.x == 0) {
        __threadfence();                            // publish this block's atomics
        int prev = atomicAdd(&g_done, 1);
        if (prev == REDBLKS - 1) {
            __threadfence();                        // see all blocks' atomics
            float cs1 = g_acc[0], cs2 = g_acc[1], mse = g_acc[2];
            float rs1 = g_acc[4], rs2 = g_acc[5];
            // t-space = dist^2/2; cd = mean_rowmin_t + mean_colmin_t
            float cd1 = rs1 / 8192.0f  + cs1 / 131072.0f;   // 8*1024, 8*16384
            float cd2 = rs2 / 16384.0f + cs2 / 262144.0f;   // 16*1024, 16*16384
            float consist = mse * (1000.0f / 49152.0f);     // mean over T*B*S*D
            out[0] = (cd1 + cd2) / 3.0f + consist;          // /(T+1)
#pragma unroll
            for (int i = 0; i < 8; i++) g_acc[i] = 0.0f;    // reset for next call
            g_done = 0;
        }
    }
}

extern "C" void kernel_launch(void* const* d_in, const int* in_sizes, int n_in,
                              void* d_out, int out_size) {
    const float* gt  = (const float*)d_in[0];   // [8,16384,3]
    const float* sp  = (const float*)d_in[1];   // [8,1024,3]
    const float* tgt = (const float*)d_in[2];   // [2,8,16384,3] -> 16 batches
    const float* tsp = (const float*)d_in[3];   // [2,8,1024,3]  -> 16 batches
    const float* M   = (const float*)d_in[4];   // [2,3,3]
    (void)in_sizes; (void)n_in; (void)out_size;

    k_chamfer<<<dim3(XGRP, 24), WARPS * 32>>>(sp, gt, tsp, tgt);
    k_red<<<REDBLKS, 256>>>(sp, tsp, M, (float*)d_out);
}

// round 17
// speedup vs baseline: 1.9167x; 1.0195x over previous
#include <cuda_runtime.h>
#include <cuda_fp16.h>

#define SD 1024          // structure points per batch (rows)
#define NP 16384         // gt points per batch (cols)
#define WC 64            // columns per warp per chunk
#define WARPS 4
#define COLS_PER_BLOCK (WARPS * WC)   // 256
#define XGRP 24          // x-groups per batch; 576 blocks total
#define REDBLKS 48

// scratch — ZERO-initialized at module load; reset inline after each read,
// so every kernel_launch call (and every graph replay) starts from zeros.
// g_rowmin holds keys: key = 0x7f800000 - float_bits(q), q >= 0. key 0 == q = +inf.
__device__ __align__(16) int g_rowmin[24576]; // 8*1024 (cham1) + 16*1024 (cham2)
__device__ float g_acc[8];  // [0]=colsum1 [1]=colsum2 [2]=mse [4]=rowsum1 [5]=rowsum2
__device__ int   g_done;    // k_red completion counter (self-resetting)

__device__ __forceinline__ unsigned h2u(__half2 h) {
    return *reinterpret_cast<unsigned*>(&h);
}
__device__ __forceinline__ unsigned umin16x2(unsigned a, unsigned b) {
    unsigned d;
    asm("min.u16x2 %0, %1, %2;" : "=r"(d) : "r"(a), "r"(b));
    return d;
}
__device__ __forceinline__ float h_lo(unsigned v) {
    return __half2float(__ushort_as_half((unsigned short)(v & 0xffffu)));
}
__device__ __forceinline__ float h_hi(unsigned v) {
    return __half2float(__ushort_as_half((unsigned short)(v >> 16)));
}

// merged chamfer, single wave: blockIdx.y in [0,24) selects job;
// blockIdx.x = j in [0,24) processes column-chunks {j, j+24, j+48} (each 256 cols).
__global__ __launch_bounds__(WARPS * 32)
void k_chamfer(const float* __restrict__ sp,  const float* __restrict__ gt,
               const float* __restrict__ tsp, const float* __restrict__ tgt)
{
    __shared__ uint4 tile[WARPS][32];        // per column: {xx,yy,zz,hh} half2 dups
    __shared__ unsigned shmin[WARPS][16][32]; // epilogue row-min staging (8 KB)
    __shared__ float shcs[WARPS];

    const int y    = blockIdx.y;
    const int jg   = blockIdx.x;        // x-group
    const int tid  = threadIdx.x;
    const int lane = tid & 31;
    const int warp = tid >> 5;
    const unsigned UBIG = 0x7bff7bffu;  // fp16 max in both halves

    const float* pa; const float* pb; int rowoff, acc_idx;
    if (y < 16) { pa = tsp + (size_t)y * SD * 3;       pb = tgt + (size_t)y * NP * 3;
                  rowoff = 8192 + y * SD;              acc_idx = 1; }
    else        { int b = y - 16;
                  pa = sp + (size_t)b * SD * 3;        pb = gt + (size_t)b * NP * 3;
                  rowoff = b * SD;                     acc_idx = 0; }

    // ---- all 1024 rows of this batch in this warp's registers (half2) ----
    // unit i packs rows (2i)*32+lane (lo half) and (2i+1)*32+lane (hi half)
    __half2 nax2[16], nay2[16], naz2[16], ha2[16];
    unsigned rl[16];
#pragma unroll
    for (int i = 0; i < 16; i++) {
        int r0 = (2 * i) * 32 + lane;
        int r1 = r0 + 32;
        float x0 = pa[r0*3+0], y0 = pa[r0*3+1], z0 = pa[r0*3+2];
        float x1 = pa[r1*3+0], y1 = pa[r1*3+1], z1 = pa[r1*3+2];
        nax2[i] = __floats2half2_rn(-x0, -x1);
        nay2[i] = __floats2half2_rn(-y0, -y1);
        naz2[i] = __floats2half2_rn(-z0, -z1);
        ha2[i]  = __floats2half2_rn(0.5f * (x0*x0 + y0*y0 + z0*z0),
                                    0.5f * (x1*x1 + y1*y1 + z1*z1));
        rl[i] = UBIG;
    }

    float csum = 0.0f;
    const int nchunks = (jg < 16) ? 3 : 2;   // chunks jg, jg+24, jg+48 (<64)

    for (int k = 0; k < nchunks; k++) {
        const int cbase = (jg + 24 * k) * COLS_PER_BLOCK + warp * WC;

        // prefetch first tile's column of this chunk
        int c = cbase + lane;
        float cx = pb[c*3+0], cy = pb[c*3+1], cz = pb[c*3+2];

#pragma unroll
        for (int t = 0; t < WC / 32; t++) {
            {   // stage: duplicated half2 packs, 16 B per column
                float hb = 0.5f * (cx*cx + cy*cy + cz*cz);
                uint4 v;
                v.x = h2u(__float2half2_rn(cx));
                v.y = h2u(__float2half2_rn(cy));
                v.z = h2u(__float2half2_rn(cz));
                v.w = h2u(__float2half2_rn(hb));
                tile[warp][lane] = v;
            }
            __syncwarp();
            if (t + 1 < WC / 32) {           // prefetch next tile from gmem
                int cn = cbase + (t + 1) * 32 + lane;
                cx = pb[cn*3+0]; cy = pb[cn*3+1]; cz = pb[cn*3+2];
            }

            // systolic: at step j, lane l owns the accumulator for column (j+l)&31.
            // q = ha + hb - dot(a,b) (= dist^2/2) in half2 (fma pipe);
            // mins as u16x2 integer min (valid for q >= 0, fp16-noise safe).
            unsigned acc = UBIG;
#pragma unroll 2
            for (int j = 0; j < 32; j++) {
                int idx = (j + lane) & 31;
                uint4 P = tile[warp][idx];
                __half2 px2 = *reinterpret_cast<__half2*>(&P.x);
                __half2 py2 = *reinterpret_cast<__half2*>(&P.y);
                __half2 pz2 = *reinterpret_cast<__half2*>(&P.z);
                __half2 hb2 = *reinterpret_cast<__half2*>(&P.w);
                unsigned c0 = UBIG, c1 = UBIG, c2 = UBIG, c3 = UBIG;
#pragma unroll
                for (int i = 0; i < 16; i += 4) {
                    unsigned q0 = h2u(__hadd2(__hfma2(nax2[i+0], px2,
                                  __hfma2(nay2[i+0], py2,
                                  __hfma2(naz2[i+0], pz2, ha2[i+0]))), hb2));
                    rl[i+0] = umin16x2(rl[i+0], q0);  c0 = umin16x2(c0, q0);
                    unsigned q1 = h2u(__hadd2(__hfma2(nax2[i+1], px2,
                                  __hfma2(nay2[i+1], py2,
                                  __hfma2(naz2[i+1], pz2, ha2[i+1]))), hb2));
                    rl[i+1] = umin16x2(rl[i+1], q1);  c1 = umin16x2(c1, q1);
                    unsigned q2 = h2u(__hadd2(__hfma2(nax2[i+2], px2,
                                  __hfma2(nay2[i+2], py2,
                                  __hfma2(naz2[i+2], pz2, ha2[i+2]))), hb2));
                    rl[i+2] = umin16x2(rl[i+2], q2);  c2 = umin16x2(c2, q2);
                    unsigned q3 = h2u(__hadd2(__hfma2(nax2[i+3], px2,
                                  __hfma2(nay2[i+3], py2,
                                  __hfma2(naz2[i+3], pz2, ha2[i+3]))), hb2));
                    rl[i+3] = umin16x2(rl[i+3], q3);  c3 = umin16x2(c3, q3);
                }
                acc = umin16x2(acc, umin16x2(umin16x2(c0, c1), umin16x2(c2, c3)));
                acc = __shfl_sync(0xffffffffu, acc, (lane + 1) & 31);
            }
            // lane l: complete 1024-row min of column l of this tile (both halves)
            csum += fminf(fmaxf(h_lo(acc), 0.0f), fmaxf(h_hi(acc), 0.0f));
            __syncwarp();
        }
    }

    // ---- epilogue: block-combine before global atomics ----
    // per-warp column-min sum -> shared; row-min units -> shared
#pragma unroll
    for (int o = 16; o > 0; o >>= 1)
        csum += __shfl_xor_sync(0xffffffffu, csum, o);
    if (lane == 0) shcs[warp] = csum;
#pragma unroll
    for (int i = 0; i < 16; i++) shmin[warp][i][lane] = rl[i];
    __syncthreads();

    if (warp == 0 && lane == 0)
        atomicAdd(&g_acc[acc_idx], shcs[0] + shcs[1] + shcs[2] + shcs[3]);

    // each warp combines 4 units across the 4 warps' partials -> global max-keys.
    // key = 0x7f800000 - float_bits(max(q,0));  atomicMax picks smallest q.
    int* rm = g_rowmin + rowoff;
#pragma unroll
    for (int u = 0; u < 4; u++) {
        int i = warp * 4 + u;
        unsigned m = umin16x2(umin16x2(shmin[0][i][lane], shmin[1][i][lane]),
                              umin16x2(shmin[2][i][lane], shmin[3][i][lane]));
        int r0 = (2 * i) * 32 + lane;
        float q0 = fmaxf(h_lo(m), 0.0f);
        float q1 = fmaxf(h_hi(m), 0.0f);
        atomicMax(&rm[r0],      0x7f800000 - __float_as_int(q0));
        atomicMax(&rm[r0 + 32], 0x7f800000 - __float_as_int(q1));
    }
}

// parallel reduction: consistency MSE + row-min key sums; resets row-min slots.
// Block-reduces through shared (3 atomics per block). The LAST block combines
// the accumulators, writes out[0], resets g_acc/g_done (replay-deterministic).
__global__ __launch_bounds__(256)
void k_red(const float* __restrict__ sp,
           const float* __restrict__ tsp,
           const float* __restrict__ M,
           float* __restrict__ out)
{
    const int gid = blockIdx.x * 256 + threadIdx.x;   // 48*256 = 12288 threads
    const int lane = threadIdx.x & 31;
    const int warp = threadIdx.x >> 5;

    // consistency: tmp[t,b,s,e] = sum_d sp[b,s,d]*M[t,d,e]; SSE vs tsp
    float e = 0.0f;
    for (int idx = gid; idx < 16384; idx += 12288) {
        int t  = idx >> 13;
        int bs = idx & 8191;
        const float* p = sp + (size_t)bs * 3;
        float x = p[0], y = p[1], z = p[2];
        const float* m = M + t * 9;
        const float* q = tsp + (size_t)idx * 3;
#pragma unroll
        for (int cc = 0; cc < 3; cc++) {
            float v = fmaf(x, m[cc], fmaf(y, m[3 + cc], z * m[6 + cc]));
            float d = v - q[cc];
            e = fmaf(d, d, e);
        }
    }

    // row-min key sums: 6144 int4 (first 2048 = chamfer1); reset after read.
    int4* rm4 = (int4*)g_rowmin;
    float a1 = 0.0f, a2 = 0.0f;
    for (int i = gid; i < 6144; i += 12288) {
        int4 v = rm4[i];
        float s = __int_as_float(0x7f800000 - v.x) + __int_as_float(0x7f800000 - v.y)
                + __int_as_float(0x7f800000 - v.z) + __int_as_float(0x7f800000 - v.w);
        rm4[i] = make_int4(0, 0, 0, 0);
        if (i < 2048) a1 += s; else a2 += s;
    }

    // warp reduce -> shared -> one atomicAdd per block per accumulator
#pragma unroll
    for (int o = 16; o > 0; o >>= 1) {
        e  += __shfl_xor_sync(0xffffffffu, e,  o);
        a1 += __shfl_xor_sync(0xffffffffu, a1, o);
        a2 += __shfl_xor_sync(0xffffffffu, a2, o);
    }
    __shared__ float ws[3][8];
    if (lane == 0) { ws[0][warp] = e; ws[1][warp] = a1; ws[2][warp] = a2; }
    __syncthreads();
    if (threadIdx.x < 3) {
        float s = 0.0f;
#pragma unroll
        for (int w = 0; w < 8; w++) s += ws[threadIdx.x][w];
        atomicAdd(&g_acc[threadIdx.x == 0 ? 2 : (threadIdx.x == 1 ? 4 : 5)], s);
    }

    // last-block-done epilogue (replaces a k_out launch)
    __syncthreads();
    if (threadIdx.x == 0) {
        __threadfence();                            // publish this block's atomics
        int prev = atomicAdd(&g_done, 1);
        if (prev == REDBLKS - 1) {
            __threadfence();                        // see all blocks' atomics
            float cs1 = g_acc[0], cs2 = g_acc[1], mse = g_acc[2];
            float rs1 = g_acc[4], rs2 = g_acc[5];
            // t-space = dist^2/2; cd = mean_rowmin_t + mean_colmin_t
            float cd1 = rs1 / 8192.0f  + cs1 / 131072.0f;   // 8*1024, 8*16384
            float cd2 = rs2 / 16384.0f + cs2 / 262144.0f;   // 16*1024, 16*16384
            float consist = mse * (1000.0f / 49152.0f);     // mean over T*B*S*D
            out[0] = (cd1 + cd2) / 3.0f + consist;          // /(T+1)
#pragma unroll
            for (int i = 0; i < 8; i++) g_acc[i] = 0.0f;    // reset for next call
            g_done = 0;
        }
    }
}

extern "C" void kernel_launch(void* const* d_in, const int* in_sizes, int n_in,
                              void* d_out, int out_size) {
    const float* gt  = (const float*)d_in[0];   // [8,16384,3]
    const float* sp  = (const float*)d_in[1];   // [8,1024,3]
    const float* tgt = (const float*)d_in[2];   // [2,8,16384,3] -> 16 batches
    const float* tsp = (const float*)d_in[3];   // [2,8,1024,3]  -> 16 batches
    const float* M   = (const float*)d_in[4];   // [2,3,3]
    (void)in_sizes; (void)n_in; (void)out_size;

    k_chamfer<<<dim3(XGRP, 24), WARPS * 32>>>(sp, gt, tsp, tgt);
    k_red<<<REDBLKS, 256>>>(sp, tsp, M, (float*)d_out);
}